// round 10
// baseline (speedup 1.0000x reference)
#include <cuda_runtime.h>
#include <cuda_bf16.h>
#include <math.h>
#include <stdint.h>

// ---- static problem config ----
namespace {
constexpr int Hc = 1024, HDc = 64, NQc = 16, NKVc = 4, Ec = 8, FFNc = 1024;
constexpr int Bc = 4, Qc = 128, Pc = 8, PSc = 128, Sq = 1024, Tc = 512;
constexpr int QKVW = HDc * (NQc + 2 * NKVc);   // 1536
constexpr float SCALEc = 0.125f;
constexpr float ALPHAc = 1.702f, LIMITc = 7.0f, EPSc = 1e-5f;
constexpr int SLOTS = 1536;
constexpr int MAXTILES = 24;
// GEMM smem: 2 stages x (AH 8K | AL 8K | BH 16K | BL 16K) = 96KB
constexpr uint32_t ASZ = 64 * 64 * 2;          // 8192
constexpr uint32_t BSZ = 128 * 64 * 2;         // 16384 (two 8KB column halves)
constexpr uint32_t STAGE = 2 * ASZ + 2 * BSZ;  // 49152
constexpr int GEMM_SMEM = 2 * (int)STAGE + 1024;
constexpr int AT_KV = 144 * 68;
constexpr int AT_Q = 4 * 16 * 64;
constexpr int AT_S = 16 * 128 * 4;
constexpr int ATT_SMEM = (2 * AT_KV + AT_Q + AT_S + 64) * 4;
}

// ---- scratch (static __device__, allocation-free) ----
__device__ float g_qkv[Tc * QKVW];
__device__ float g_h[Tc * Hc];
__device__ __nv_bfloat16 g_xnh[Tc * Hc], g_xnl[Tc * Hc];
__device__ __nv_bfloat16 g_ath[Tc * Hc], g_atl[Tc * Hc];
__device__ __nv_bfloat16 g_x2h[Tc * Hc], g_x2l[Tc * Hc];
__device__ __nv_bfloat16 g_act_hi[SLOTS * FFNc], g_act_lo[SLOTS * FFNc];
__device__ float g_eo[SLOTS * Hc];
__device__ int   g_eidx[Tc * 2];
__device__ float g_ewt[Tc * 2];
__device__ int   g_cnt[Ec];
__device__ int   g_poff[Ec];
__device__ int   g_tok[SLOTS];      // -1 = ghost slot
__device__ int   g_slotof[Tc * 2];
__device__ int   g_tile_e[MAXTILES];
__device__ int   g_ntiles;
// split weights, native [K][N] layout, bf16 hi/lo
__device__ __nv_bfloat16 g_wqh[Hc * QKVW], g_wql[Hc * QKVW];
__device__ __nv_bfloat16 g_woh[Hc * Hc], g_wol[Hc * Hc];
__device__ __nv_bfloat16 g_wguh[Ec * Hc * 2 * FFNc], g_wgul[Ec * Hc * 2 * FFNc];
__device__ __nv_bfloat16 g_wdh[Ec * FFNc * Hc], g_wdl[Ec * FFNc * Hc];

// ============================================================
__device__ __forceinline__ uint32_t smem_to_u32(const void* p) {
    uint32_t a;
    asm("{ .reg .u64 t; cvta.to.shared.u64 t, %1; cvt.u32.u64 %0, t; }" : "=r"(a) : "l"(p));
    return a;
}
__device__ __forceinline__ void ldm_x4(uint32_t& r0, uint32_t& r1, uint32_t& r2,
                                       uint32_t& r3, uint32_t addr) {
    asm volatile("ldmatrix.sync.aligned.m8n8.x4.shared.b16 {%0,%1,%2,%3}, [%4];"
                 : "=r"(r0), "=r"(r1), "=r"(r2), "=r"(r3) : "r"(addr));
}
__device__ __forceinline__ void ldm_x4_t(uint32_t& r0, uint32_t& r1, uint32_t& r2,
                                         uint32_t& r3, uint32_t addr) {
    asm volatile("ldmatrix.sync.aligned.m8n8.x4.trans.shared.b16 {%0,%1,%2,%3}, [%4];"
                 : "=r"(r0), "=r"(r1), "=r"(r2), "=r"(r3) : "r"(addr));
}
__device__ __forceinline__ void mma_bf16(float* c, const uint32_t* a, const uint32_t* b) {
    asm volatile(
        "mma.sync.aligned.m16n8k16.row.col.f32.bf16.bf16.f32 "
        "{%0,%1,%2,%3}, {%4,%5,%6,%7}, {%8,%9}, {%0,%1,%2,%3};"
        : "+f"(c[0]), "+f"(c[1]), "+f"(c[2]), "+f"(c[3])
        : "r"(a[0]), "r"(a[1]), "r"(a[2]), "r"(a[3]), "r"(b[0]), "r"(b[1]));
}
__device__ __forceinline__ void cp16(uint32_t dst, const void* src, bool pred) {
    int sz = pred ? 16 : 0;
    asm volatile("cp.async.cg.shared.global [%0], [%1], 16, %2;"
                 :: "r"(dst), "l"(src), "r"(sz) : "memory");
}
#define CP_COMMIT() asm volatile("cp.async.commit_group;" ::: "memory")

// ============================================================
// Dual-range streaming weight conversion (fp32 -> bf16 hi/lo)
// ============================================================
__device__ __forceinline__ void conv_one(const float4* __restrict__ src,
                                         uint2* __restrict__ dh,
                                         uint2* __restrict__ dl, int i) {
    float4 v = src[i];
    __nv_bfloat16 h0 = __float2bfloat16(v.x), h1 = __float2bfloat16(v.y);
    __nv_bfloat16 h2 = __float2bfloat16(v.z), h3 = __float2bfloat16(v.w);
    uint2 hh, ll;
    hh.x = ((uint32_t)__bfloat16_as_ushort(h1) << 16) | __bfloat16_as_ushort(h0);
    hh.y = ((uint32_t)__bfloat16_as_ushort(h3) << 16) | __bfloat16_as_ushort(h2);
    __nv_bfloat16 l0 = __float2bfloat16(v.x - __bfloat162float(h0));
    __nv_bfloat16 l1 = __float2bfloat16(v.y - __bfloat162float(h1));
    __nv_bfloat16 l2 = __float2bfloat16(v.z - __bfloat162float(h2));
    __nv_bfloat16 l3 = __float2bfloat16(v.w - __bfloat162float(h3));
    ll.x = ((uint32_t)__bfloat16_as_ushort(l1) << 16) | __bfloat16_as_ushort(l0);
    ll.y = ((uint32_t)__bfloat16_as_ushort(l3) << 16) | __bfloat16_as_ushort(l2);
    dh[i] = hh;
    dl[i] = ll;
}
__global__ void convert2_kernel(const float4* __restrict__ s1, uint2* __restrict__ dh1,
                                uint2* __restrict__ dl1, int n1,
                                const float4* __restrict__ s2, uint2* __restrict__ dh2,
                                uint2* __restrict__ dl2, int n2) {
    int i = blockIdx.x * blockDim.x + threadIdx.x;
    if (i < n1) {
        conv_one(s1, dh1, dl1, i);
    } else {
        i -= n1;
        if (i < n2) conv_one(s2, dh2, dl2, i);
    }
}

// ============================================================
// HMMA GEMM, 64x128 C tile, 512 threads (4x4 warps, 16x32 warp tile),
// split-bf16 (3 MMA), 2-stage cp.async, split-K via blockIdx.z (modes 0/1/3).
// Accumulation into pre-zeroed output via atomicAdd; bias/resid from split 0.
// MODE: 0=QKV, 1=OPROJ(+resid), 2=GATEUP full-K (gather+swiglu->act), 3=DOWN(->eo)
// ============================================================
template <int MODE, int NN>
__global__ __launch_bounds__(512, 1) void mma_gemm(
    const __nv_bfloat16* __restrict__ Ah, const __nv_bfloat16* __restrict__ Al,
    const __nv_bfloat16* __restrict__ Bh, const __nv_bfloat16* __restrict__ Bl,
    const float* __restrict__ bias, const float* __restrict__ resid,
    float* __restrict__ Cout) {
    extern __shared__ __align__(1024) char dsm[];
    __shared__ int s_tok[64];

    const int tid = threadIdx.x, wid = tid >> 5, lane = tid & 31;
    const int wm = wid & 3, wn = wid >> 2;   // 4x4 warp grid; warp tile 16x32
    const int row0 = blockIdx.y * 64, col0 = blockIdx.x * 128;
    const int kz = (MODE == 2) ? 0 : (int)blockIdx.z;
    const int NKB = (MODE == 2) ? 16 : 8;
    int e = 0, lb = 0, cnt = Tc;
    if (MODE >= 2) {
        if ((int)blockIdx.y >= g_ntiles) return;
        e = g_tile_e[blockIdx.y];
        lb = row0 - g_poff[e];
        cnt = g_cnt[e];
    }
    const __nv_bfloat16* Bhg = Bh + (MODE >= 2 ? (size_t)e * 1024 * NN : 0);
    const __nv_bfloat16* Blg = Bl + (MODE >= 2 ? (size_t)e * 1024 * NN : 0);

    uint32_t base = (smem_to_u32(dsm) + 1023) & ~1023u;

    if (MODE == 2 && tid < 64) s_tok[tid] = g_tok[row0 + tid];
    if (MODE == 2) __syncthreads();

    // ---- issue one K-block stage: A[64m][64k] hi/lo, B[64k][128n] hi/lo ----
    auto issue_stage = [&](int kb, uint32_t buf) {
        const int kbase = (kz * NKB + kb) * 64;
        {   // A: 512 chunks, one per thread
            int c = tid;
            int row = c >> 3, k8 = c & 7;
            uint32_t raw = row * 128 + k8 * 16;
            uint32_t sw = raw ^ ((raw >> 3) & 0x70);
            size_t o;
            bool pred = true;
            if (MODE == 2) {
                int tok = s_tok[row];
                pred = tok >= 0;
                o = (size_t)(pred ? tok : 0) * 1024 + kbase + k8 * 8;
            } else if (MODE == 3) {
                pred = (lb + row) < cnt;
                o = (size_t)(row0 + row) * 1024 + kbase + k8 * 8;
            } else {
                o = (size_t)(row0 + row) * 1024 + kbase + k8 * 8;
            }
            cp16(buf + sw, Ah + o, pred);
            cp16(buf + ASZ + sw, Al + o, pred);
        }
#pragma unroll
        for (int i = 0; i < 2; i++) {      // B: 1024 chunks (2 halves)
            int c = tid + 512 * i;
            int row = c >> 4;              // k row 0..63
            int j = c & 15;
            int half = j >> 3, k8 = j & 7;
            uint32_t raw = row * 128 + k8 * 16;
            uint32_t sw = (raw ^ ((raw >> 3) & 0x70)) + half * 8192;
            size_t o = (size_t)(kbase + row) * NN + col0 + j * 8;
            cp16(buf + 2 * ASZ + sw, Bhg + o, true);
            cp16(buf + 2 * ASZ + BSZ + sw, Blg + o, true);
        }
        CP_COMMIT();
    };

    float acc[4][4] = {};

    const uint32_t a_raw0 = (uint32_t)(wm * 16 + (lane & 15)) * 128 + (lane >> 4) * 16;
    const int bm = lane >> 3;
    const uint32_t b_raw0 = (uint32_t)((bm & 1) * 8 + (lane & 7)) * 128 +
                            (uint32_t)((wn & 1) * 32 + (bm >> 1) * 8) * 2;
    const uint32_t b_half = (uint32_t)(wn >> 1) * 8192;

    auto compute = [&](uint32_t buf) {
        uint32_t AH = buf, AL = buf + ASZ;
        uint32_t BH = buf + 2 * ASZ + b_half, BL = BH + BSZ;
#pragma unroll
        for (int ks = 0; ks < 4; ks++) {
            uint32_t ah[4], al[4], bh[4][2], bl[4][2];
            {
                uint32_t raw = a_raw0 + ks * 32;
                uint32_t sw = raw ^ ((raw >> 3) & 0x70);
                ldm_x4(ah[0], ah[1], ah[2], ah[3], AH + sw);
                ldm_x4(al[0], al[1], al[2], al[3], AL + sw);
            }
#pragma unroll
            for (int p = 0; p < 2; p++) {
                uint32_t raw = b_raw0 + p * 32 + ks * 2048;
                uint32_t sw = raw ^ ((raw >> 3) & 0x70);
                ldm_x4_t(bh[2 * p][0], bh[2 * p][1], bh[2 * p + 1][0], bh[2 * p + 1][1],
                         BH + sw);
                ldm_x4_t(bl[2 * p][0], bl[2 * p][1], bl[2 * p + 1][0], bl[2 * p + 1][1],
                         BL + sw);
            }
#pragma unroll
            for (int ni = 0; ni < 4; ni++) {
                mma_bf16(acc[ni], ah, bh[ni]);
                mma_bf16(acc[ni], ah, bl[ni]);
                mma_bf16(acc[ni], al, bh[ni]);
            }
        }
    };

    issue_stage(0, base);
    issue_stage(1, base + STAGE);
    for (int kb = 0; kb < NKB; kb++) {
        if (kb < NKB - 1)
            asm volatile("cp.async.wait_group 1;" ::: "memory");
        else
            asm volatile("cp.async.wait_group 0;" ::: "memory");
        __syncthreads();
        uint32_t buf = base + (uint32_t)(kb & 1) * STAGE;
        compute(buf);
        __syncthreads();
        if (kb + 2 < NKB) issue_stage(kb + 2, buf);
    }

    // ---- epilogue ----
    const int g = lane >> 2, tg = lane & 3;
#pragma unroll
    for (int ni = 0; ni < 4; ni++) {
#pragma unroll
        for (int hh = 0; hh < 2; hh++) {
            int rt = wm * 16 + g + hh * 8;
            int c = col0 + wn * 32 + ni * 8 + tg * 2;
            float v0 = acc[ni][2 * hh + 0];
            float v1 = acc[ni][2 * hh + 1];
            if (MODE == 0) {
                size_t p = (size_t)(row0 + rt) * NN + c;
                if (kz == 0) { v0 += bias[c]; v1 += bias[c + 1]; }
                atomicAdd(&Cout[p], v0);
                atomicAdd(&Cout[p + 1], v1);
            } else if (MODE == 1) {
                size_t p = (size_t)(row0 + rt) * NN + c;
                if (kz == 0) {
                    v0 += bias[c] + resid[p];
                    v1 += bias[c + 1] + resid[p + 1];
                }
                atomicAdd(&Cout[p], v0);
                atomicAdd(&Cout[p + 1], v1);
            } else if (MODE == 2) {
                if (lb + rt < cnt) {
                    const float* bg = bias + (size_t)e * 2 * FFNc;
                    float gv = v0 + bg[c];
                    float uv = v1 + bg[c + 1];
                    gv = fminf(gv, LIMITc);
                    uv = fminf(fmaxf(uv, -LIMITc), LIMITc);
                    float glu = gv / (1.0f + expf(-ALPHAc * gv));
                    float a = (uv + 1.0f) * glu;
                    __nv_bfloat16 h = __float2bfloat16(a);
                    __nv_bfloat16 l = __float2bfloat16(a - __bfloat162float(h));
                    size_t p = (size_t)(row0 + rt) * FFNc + (c >> 1);
                    g_act_hi[p] = h;
                    g_act_lo[p] = l;
                }
            } else {
                if (lb + rt < cnt) {
                    size_t p = (size_t)(row0 + rt) * Hc + c;
                    if (kz == 0) {
                        const float* bd = bias + (size_t)e * Hc;
                        v0 += bd[c];
                        v1 += bd[c + 1];
                    }
                    atomicAdd(&g_eo[p], v0);
                    atomicAdd(&g_eo[p + 1], v1);
                }
            }
        }
    }
}

// ============================================================
// RMSNorm (ln1) -> bf16 hi/lo split
// ============================================================
__global__ void rmsnorm1_kernel(const float* __restrict__ x,
                                const float* __restrict__ w) {
    int t = blockIdx.x, tid = threadIdx.x;
    const float* xr = x + (size_t)t * Hc;
    float ss = 0.f;
#pragma unroll
    for (int i = 0; i < 4; i++) { float v = xr[tid + 256 * i]; ss += v * v; }
#pragma unroll
    for (int o = 16; o; o >>= 1) ss += __shfl_xor_sync(~0u, ss, o);
    __shared__ float red[8];
    if ((tid & 31) == 0) red[tid >> 5] = ss;
    __syncthreads();
    float tot = 0.f;
#pragma unroll
    for (int i = 0; i < 8; i++) tot += red[i];
    float rinv = rsqrtf(tot * (1.0f / Hc) + EPSc);
#pragma unroll
    for (int i = 0; i < 4; i++) {
        int c = tid + 256 * i;
        float v = xr[c] * w[c] * rinv;
        __nv_bfloat16 h = __float2bfloat16(v);
        g_xnh[(size_t)t * Hc + c] = h;
        g_xnl[(size_t)t * Hc + c] = __float2bfloat16(v - __bfloat162float(h));
    }
}

// ============================================================
// Tiled windowed GQA attention with sink
// ============================================================
__global__ __launch_bounds__(256, 1) void attn_kernel(
    const float* __restrict__ qkvb, const float* __restrict__ kvc,
    const int* __restrict__ pidx, const float* __restrict__ sinks) {
    extern __shared__ float sm[];
    float* Ks = sm;
    float* Vs = Ks + AT_KV;
    float* Qs = Vs + AT_KV;
    float* Ss = Qs + AT_Q;
    float* Rd = Ss + AT_S;

    const int qt = blockIdx.x, kvh = blockIdx.y, b = blockIdx.z;
    const int q0 = qt * 16;
    const int tid = threadIdx.x;

    for (int i = tid; i < 143 * 16; i += 256) {
        int kk = i >> 4, d = (i & 15) * 4;
        int kpos = 769 + q0 + kk;
        const float *kp, *vp;
        if (kpos >= Sq - Qc) {
            int tt = b * Qc + (kpos - (Sq - Qc));
            kp = qkvb + (size_t)tt * QKVW + (NQc + kvh) * HDc + d;
            vp = qkvb + (size_t)tt * QKVW + (NQc + NKVc + kvh) * HDc + d;
        } else {
            int pg = pidx[b * Pc + (kpos >> 7)];
            size_t bb = ((size_t)(pg * 2) * PSc + (kpos & 127)) * (NKVc * HDc) + kvh * HDc + d;
            kp = kvc + bb;
            vp = kvc + bb + (size_t)PSc * NKVc * HDc;
        }
        *(float4*)(Ks + kk * 68 + d) = *(const float4*)kp;
        *(float4*)(Vs + kk * 68 + d) = *(const float4*)vp;
    }
    for (int i = tid; i < 1024; i += 256) {
        int h = i >> 8, qq = (i >> 4) & 15, d = (i & 15) * 4;
        int t = b * Qc + q0 + qq;
        float4 v = *(const float4*)(qkvb + (size_t)t * QKVW + (kvh * 4 + h) * HDc + d);
        v.x *= SCALEc; v.y *= SCALEc; v.z *= SCALEc; v.w *= SCALEc;
        *(float4*)(Qs + (h * 16 + qq) * 64 + d) = v;
    }
    __syncthreads();

    {
        const int qq = tid >> 4, lane = tid & 15;
        float acc[8][4];
#pragma unroll
        for (int j = 0; j < 8; j++)
#pragma unroll
            for (int h = 0; h < 4; h++) acc[j][h] = 0.f;
#pragma unroll
        for (int dc = 0; dc < 4; dc++) {
            float4 qr[4][4];
#pragma unroll
            for (int h = 0; h < 4; h++)
#pragma unroll
                for (int dd = 0; dd < 4; dd++)
                    qr[h][dd] = *(float4*)(Qs + (h * 16 + qq) * 64 + dc * 16 + dd * 4);
#pragma unroll
            for (int j = 0; j < 8; j++) {
                int kk = qq + lane + 16 * j;
                const float* kr = Ks + kk * 68 + dc * 16;
#pragma unroll
                for (int dd = 0; dd < 4; dd++) {
                    float4 k4 = *(const float4*)(kr + dd * 4);
#pragma unroll
                    for (int h = 0; h < 4; h++)
                        acc[j][h] += qr[h][dd].x * k4.x + qr[h][dd].y * k4.y +
                                     qr[h][dd].z * k4.z + qr[h][dd].w * k4.w;
                }
            }
        }
#pragma unroll
        for (int j = 0; j < 8; j++) {
            int l = lane + 16 * j;
#pragma unroll
            for (int h = 0; h < 4; h++) Ss[(qq * 128 + l) * 4 + h] = acc[j][h];
        }
    }
    __syncthreads();

    {
        const int row = tid >> 2, l2 = tid & 3;
        const int sq = row >> 2, sh = row & 3;
        float m = -1e30f;
        for (int k = l2; k < 128; k += 4) m = fmaxf(m, Ss[(sq * 128 + k) * 4 + sh]);
        m = fmaxf(m, __shfl_xor_sync(~0u, m, 1));
        m = fmaxf(m, __shfl_xor_sync(~0u, m, 2));
        float sum = 0.f;
        for (int k = l2; k < 128; k += 4) {
            float p = expf(Ss[(sq * 128 + k) * 4 + sh] - m);
            Ss[(sq * 128 + k) * 4 + sh] = p;
            sum += p;
        }
        sum += __shfl_xor_sync(~0u, sum, 1);
        sum += __shfl_xor_sync(~0u, sum, 2);
        if (l2 == 0) Rd[sq * 4 + sh] = 1.0f / (sum + expf(sinks[kvh * 4 + sh] - m));
    }
    __syncthreads();

    {
        const int qq = tid >> 4, lane = tid & 15;
        const int d = lane * 4;
        float4 oa[4];
#pragma unroll
        for (int h = 0; h < 4; h++) oa[h] = make_float4(0.f, 0.f, 0.f, 0.f);
        for (int l = 0; l < 128; l++) {
            float4 v = *(const float4*)(Vs + (qq + l) * 68 + d);
            const float* pr = Ss + (qq * 128 + l) * 4;
#pragma unroll
            for (int h = 0; h < 4; h++) {
                float p = pr[h];
                oa[h].x += p * v.x; oa[h].y += p * v.y;
                oa[h].z += p * v.z; oa[h].w += p * v.w;
            }
        }
        int t = b * Qc + q0 + qq;
#pragma unroll
        for (int h = 0; h < 4; h++) {
            float r = Rd[qq * 4 + h];
            float x0 = oa[h].x * r, x1 = oa[h].y * r, x2 = oa[h].z * r, x3 = oa[h].w * r;
            size_t p2 = (size_t)t * Hc + (kvh * 4 + h) * HDc + d;
            uint2 hh, ll;
            __nv_bfloat16 b0 = __float2bfloat16(x0), b1 = __float2bfloat16(x1);
            __nv_bfloat16 b2 = __float2bfloat16(x2), b3 = __float2bfloat16(x3);
            hh.x = ((uint32_t)__bfloat16_as_ushort(b1) << 16) | __bfloat16_as_ushort(b0);
            hh.y = ((uint32_t)__bfloat16_as_ushort(b3) << 16) | __bfloat16_as_ushort(b2);
            __nv_bfloat16 c0 = __float2bfloat16(x0 - __bfloat162float(b0));
            __nv_bfloat16 c1 = __float2bfloat16(x1 - __bfloat162float(b1));
            __nv_bfloat16 c2 = __float2bfloat16(x2 - __bfloat162float(b2));
            __nv_bfloat16 c3 = __float2bfloat16(x3 - __bfloat162float(b3));
            ll.x = ((uint32_t)__bfloat16_as_ushort(c1) << 16) | __bfloat16_as_ushort(c0);
            ll.y = ((uint32_t)__bfloat16_as_ushort(c3) << 16) | __bfloat16_as_ushort(c2);
            *(uint2*)(g_ath + p2) = hh;
            *(uint2*)(g_atl + p2) = ll;
        }
    }
}

// ============================================================
// Router: rmsnorm(ln2) -> x2 (bf16 split), logits, top-2 weights
// ============================================================
__global__ void router_kernel(const float* __restrict__ ln2,
                              const float* __restrict__ Wr,
                              const float* __restrict__ br) {
    int t = blockIdx.x, tid = threadIdx.x;
    __shared__ float sx[Hc];
    __shared__ float red[8];
    __shared__ float lg[Ec];
    const float* hr = g_h + (size_t)t * Hc;
    float ss = 0.f;
#pragma unroll
    for (int i = 0; i < 4; i++) { float v = hr[tid + 256 * i]; ss += v * v; }
#pragma unroll
    for (int o = 16; o; o >>= 1) ss += __shfl_xor_sync(~0u, ss, o);
    if ((tid & 31) == 0) red[tid >> 5] = ss;
    __syncthreads();
    float tot = 0.f;
#pragma unroll
    for (int i = 0; i < 8; i++) tot += red[i];
    float rinv = rsqrtf(tot * (1.0f / Hc) + EPSc);
#pragma unroll
    for (int i = 0; i < 4; i++) {
        int c = tid + 256 * i;
        float v = hr[c] * ln2[c] * rinv;
        sx[c] = v;
        __nv_bfloat16 hb = __float2bfloat16(v);
        g_x2h[(size_t)t * Hc + c] = hb;
        g_x2l[(size_t)t * Hc + c] = __float2bfloat16(v - __bfloat162float(hb));
    }
    __syncthreads();
    int w = tid >> 5, lane = tid & 31;
    float s = 0.f;
    for (int c = lane; c < Hc; c += 32) s += sx[c] * Wr[c * Ec + w];
#pragma unroll
    for (int o = 16; o; o >>= 1) s += __shfl_xor_sync(~0u, s, o);
    if (lane == 0) lg[w] = s + br[w];
    __syncthreads();
    if (tid == 0) {
        int i0 = 0; float v0 = lg[0];
#pragma unroll
        for (int e = 1; e < Ec; e++) if (lg[e] > v0) { v0 = lg[e]; i0 = e; }
        int i1 = -1; float v1 = -1e30f;
#pragma unroll
        for (int e = 0; e < Ec; e++) {
            if (e == i0) continue;
            if (lg[e] > v1) { v1 = lg[e]; i1 = e; }
        }
        float e1 = expf(v1 - v0);
        g_eidx[t * 2] = i0; g_eidx[t * 2 + 1] = i1;
        g_ewt[t * 2] = 1.0f / (1.0f + e1);
        g_ewt[t * 2 + 1] = e1 / (1.0f + e1);
    }
}

// ============================================================
// Bucket tokens by expert with 64-aligned padded regions + tile map
// ============================================================
__global__ void bucket_kernel() {
    __shared__ int c1[Ec], c2[Ec], po[Ec];
    int tid = threadIdx.x;
    if (tid < Ec) { c1[tid] = 0; c2[tid] = 0; }
    for (int i = tid; i < SLOTS; i += 256) g_tok[i] = -1;
    __syncthreads();
    for (int i = tid; i < Tc * 2; i += 256) atomicAdd(&c1[g_eidx[i]], 1);
    __syncthreads();
    if (tid == 0) {
        int run = 0, nt = 0;
        for (int e = 0; e < Ec; e++) {
            po[e] = run;
            g_poff[e] = run;
            int te = (c1[e] + 63) >> 6;
            for (int j = 0; j < te; j++) g_tile_e[nt++] = e;
            run += te * 64;
        }
        g_ntiles = nt;
    }
    __syncthreads();
    if (tid < Ec) g_cnt[tid] = c1[tid];
    for (int i = tid; i < Tc * 2; i += 256) {
        int e = g_eidx[i];
        int r = atomicAdd(&c2[e], 1);
        int slot = po[e] + r;
        g_tok[slot] = i >> 1;
        g_slotof[i] = slot;
    }
}

// ============================================================
// Final combine
// ============================================================
__global__ void combine_kernel(float* __restrict__ out) {
    int t = blockIdx.x, tid = threadIdx.x;
    float w0 = g_ewt[t * 2], w1 = g_ewt[t * 2 + 1];
    int s0 = g_slotof[t * 2], s1 = g_slotof[t * 2 + 1];
#pragma unroll
    for (int i = 0; i < 4; i++) {
        int c = tid + 256 * i;
        out[(size_t)t * Hc + c] = g_h[(size_t)t * Hc + c]
                                + w0 * g_eo[(size_t)s0 * Hc + c]
                                + w1 * g_eo[(size_t)s1 * Hc + c];
    }
}

// ============================================================
extern "C" void kernel_launch(void* const* d_in, const int* in_sizes, int n_in,
                              void* d_out, int out_size) {
    const float* hidden = (const float*)d_in[0];
    const float* kvc    = (const float*)d_in[1];
    const int*   pidx   = (const int*)d_in[3];
    const float* sinks  = (const float*)d_in[4];
    const float* w_qkv  = (const float*)d_in[5];
    const float* b_qkv  = (const float*)d_in[6];
    const float* w_o    = (const float*)d_in[7];
    const float* b_o    = (const float*)d_in[8];
    const float* ln1    = (const float*)d_in[9];
    const float* ln2    = (const float*)d_in[10];
    const float* w_r    = (const float*)d_in[11];
    const float* b_r    = (const float*)d_in[12];
    const float* w_gu   = (const float*)d_in[13];
    const float* b_gu   = (const float*)d_in[14];
    const float* w_d    = (const float*)d_in[15];
    const float* b_d    = (const float*)d_in[16];
    float* out = (float*)d_out;

    void *pq, *ph, *peo;
    void *pxh, *pxl, *pah, *pal, *px2h, *px2l, *pacth, *pactl;
    void *pwqh, *pwql, *pwoh, *pwol, *pwguh, *pwgul, *pwdh, *pwdl;
    cudaGetSymbolAddress(&pq, g_qkv);
    cudaGetSymbolAddress(&ph, g_h);
    cudaGetSymbolAddress(&peo, g_eo);
    cudaGetSymbolAddress(&pxh, g_xnh);  cudaGetSymbolAddress(&pxl, g_xnl);
    cudaGetSymbolAddress(&pah, g_ath);  cudaGetSymbolAddress(&pal, g_atl);
    cudaGetSymbolAddress(&px2h, g_x2h); cudaGetSymbolAddress(&px2l, g_x2l);
    cudaGetSymbolAddress(&pacth, g_act_hi); cudaGetSymbolAddress(&pactl, g_act_lo);
    cudaGetSymbolAddress(&pwqh, g_wqh); cudaGetSymbolAddress(&pwql, g_wql);
    cudaGetSymbolAddress(&pwoh, g_woh); cudaGetSymbolAddress(&pwol, g_wol);
    cudaGetSymbolAddress(&pwguh, g_wguh); cudaGetSymbolAddress(&pwgul, g_wgul);
    cudaGetSymbolAddress(&pwdh, g_wdh);   cudaGetSymbolAddress(&pwdl, g_wdl);

    cudaFuncSetAttribute(mma_gemm<0, QKVW>, cudaFuncAttributeMaxDynamicSharedMemorySize, GEMM_SMEM);
    cudaFuncSetAttribute(mma_gemm<1, Hc>, cudaFuncAttributeMaxDynamicSharedMemorySize, GEMM_SMEM);
    cudaFuncSetAttribute(mma_gemm<2, 2 * FFNc>, cudaFuncAttributeMaxDynamicSharedMemorySize, GEMM_SMEM);
    cudaFuncSetAttribute(mma_gemm<3, Hc>, cudaFuncAttributeMaxDynamicSharedMemorySize, GEMM_SMEM);
    cudaFuncSetAttribute(attn_kernel, cudaFuncAttributeMaxDynamicSharedMemorySize, ATT_SMEM);

    // ---- side stream for weight converts (fork/join, capture-safe) ----
    cudaStream_t s1;
    cudaStreamCreate(&s1);
    cudaEvent_t e0, e1, e2;
    cudaEventCreateWithFlags(&e0, cudaEventDisableTiming);
    cudaEventCreateWithFlags(&e1, cudaEventDisableTiming);
    cudaEventCreateWithFlags(&e2, cudaEventDisableTiming);

    cudaEventRecord(e0, 0);
    cudaStreamWaitEvent(s1, e0, 0);
    {
        int n1 = Hc * QKVW / 4, n2 = Hc * Hc / 4;
        convert2_kernel<<<(n1 + n2 + 255) / 256, 256, 0, s1>>>(
            (const float4*)w_qkv, (uint2*)pwqh, (uint2*)pwql, n1,
            (const float4*)w_o, (uint2*)pwoh, (uint2*)pwol, n2);
        cudaEventRecord(e1, s1);
        int n3 = Ec * Hc * 2 * FFNc / 4, n4 = Ec * FFNc * Hc / 4;
        convert2_kernel<<<(n3 + n4 + 255) / 256, 256, 0, s1>>>(
            (const float4*)w_gu, (uint2*)pwguh, (uint2*)pwgul, n3,
            (const float4*)w_d, (uint2*)pwdh, (uint2*)pwdl, n4);
        cudaEventRecord(e2, s1);
    }

    // main stream: zero split-K accumulators, then pipeline
    cudaMemsetAsync(pq, 0, sizeof(float) * Tc * QKVW, 0);
    cudaMemsetAsync(ph, 0, sizeof(float) * Tc * Hc, 0);
    cudaMemsetAsync(peo, 0, sizeof(float) * SLOTS * Hc, 0);
    rmsnorm1_kernel<<<Tc, 256>>>(hidden, ln1);
    cudaStreamWaitEvent(0, e1, 0);
    mma_gemm<0, QKVW><<<dim3(QKVW / 128, Tc / 64, 2), 512, GEMM_SMEM>>>(
        (const __nv_bfloat16*)pxh, (const __nv_bfloat16*)pxl,
        (const __nv_bfloat16*)pwqh, (const __nv_bfloat16*)pwql,
        b_qkv, nullptr, (float*)pq);
    attn_kernel<<<dim3(8, NKVc, Bc), 256, ATT_SMEM>>>(
        (const float*)pq, kvc, pidx, sinks);
    mma_gemm<1, Hc><<<dim3(Hc / 128, Tc / 64, 2), 512, GEMM_SMEM>>>(
        (const __nv_bfloat16*)pah, (const __nv_bfloat16*)pal,
        (const __nv_bfloat16*)pwoh, (const __nv_bfloat16*)pwol,
        b_o, hidden, (float*)ph);
    router_kernel<<<Tc, 256>>>(ln2, w_r, b_r);
    bucket_kernel<<<1, 256>>>();
    cudaStreamWaitEvent(0, e2, 0);
    mma_gemm<2, 2 * FFNc><<<dim3(2 * FFNc / 128, MAXTILES, 1), 512, GEMM_SMEM>>>(
        (const __nv_bfloat16*)px2h, (const __nv_bfloat16*)px2l,
        (const __nv_bfloat16*)pwguh, (const __nv_bfloat16*)pwgul,
        b_gu, nullptr, nullptr);
    mma_gemm<3, Hc><<<dim3(Hc / 128, MAXTILES, 2), 512, GEMM_SMEM>>>(
        (const __nv_bfloat16*)pacth, (const __nv_bfloat16*)pactl,
        (const __nv_bfloat16*)pwdh, (const __nv_bfloat16*)pwdl,
        b_d, nullptr, nullptr);
    combine_kernel<<<Tc, 256>>>(out);
}

// round 11
// speedup vs baseline: 1.1971x; 1.1971x over previous
#include <cuda_runtime.h>
#include <cuda_bf16.h>
#include <math.h>
#include <stdint.h>

// ---- static problem config ----
namespace {
constexpr int Hc = 1024, HDc = 64, NQc = 16, NKVc = 4, Ec = 8, FFNc = 1024;
constexpr int Bc = 4, Qc = 128, Pc = 8, PSc = 128, Sq = 1024, Tc = 512;
constexpr int QKVW = HDc * (NQc + 2 * NKVc);   // 1536
constexpr float SCALEc = 0.125f;
constexpr float ALPHAc = 1.702f, LIMITc = 7.0f, EPSc = 1e-5f;
constexpr int SLOTS = 1536;
constexpr int MAXTILES = 24;
// GEMM smem: 3 stages x (AH 8K | AL 8K | BH 8K | BL 8K) = 96KB -> 2 CTAs/SM
constexpr uint32_t ASZ = 64 * 64 * 2;
constexpr uint32_t BSZ = 64 * 64 * 2;
constexpr uint32_t STAGE = 2 * ASZ + 2 * BSZ;  // 32768
constexpr int NSTAGE = 3;
constexpr int GEMM_SMEM = NSTAGE * (int)STAGE + 1024;
constexpr int AT_KV = 144 * 68;
constexpr int AT_Q = 4 * 16 * 64;
constexpr int AT_S = 16 * 128 * 4;
constexpr int ATT_SMEM = (2 * AT_KV + AT_Q + AT_S + 64) * 4;
}

// ---- scratch (static __device__, allocation-free) ----
__device__ float g_qkv[Tc * QKVW];
__device__ float g_h[Tc * Hc];
__device__ __nv_bfloat16 g_xnh[Tc * Hc], g_xnl[Tc * Hc];
__device__ __nv_bfloat16 g_ath[Tc * Hc], g_atl[Tc * Hc];
__device__ __nv_bfloat16 g_x2h[Tc * Hc], g_x2l[Tc * Hc];
__device__ __nv_bfloat16 g_act_hi[SLOTS * FFNc], g_act_lo[SLOTS * FFNc];
__device__ float g_eo[SLOTS * Hc];
__device__ int   g_eidx[Tc * 2];
__device__ float g_ewt[Tc * 2];
__device__ int   g_cnt[Ec];
__device__ int   g_poff[Ec];
__device__ int   g_tok[SLOTS];      // -1 = ghost slot
__device__ int   g_slotof[Tc * 2];
__device__ int   g_tile_e[MAXTILES];
__device__ int   g_ntiles;
// split weights, native [K][N] layout, bf16 hi/lo
__device__ __nv_bfloat16 g_wqh[Hc * QKVW], g_wql[Hc * QKVW];
__device__ __nv_bfloat16 g_woh[Hc * Hc], g_wol[Hc * Hc];
__device__ __nv_bfloat16 g_wguh[Ec * Hc * 2 * FFNc], g_wgul[Ec * Hc * 2 * FFNc];
__device__ __nv_bfloat16 g_wdh[Ec * FFNc * Hc], g_wdl[Ec * FFNc * Hc];

// ============================================================
__device__ __forceinline__ uint32_t smem_to_u32(const void* p) {
    uint32_t a;
    asm("{ .reg .u64 t; cvta.to.shared.u64 t, %1; cvt.u32.u64 %0, t; }" : "=r"(a) : "l"(p));
    return a;
}
__device__ __forceinline__ void ldm_x4(uint32_t& r0, uint32_t& r1, uint32_t& r2,
                                       uint32_t& r3, uint32_t addr) {
    asm volatile("ldmatrix.sync.aligned.m8n8.x4.shared.b16 {%0,%1,%2,%3}, [%4];"
                 : "=r"(r0), "=r"(r1), "=r"(r2), "=r"(r3) : "r"(addr));
}
__device__ __forceinline__ void ldm_x4_t(uint32_t& r0, uint32_t& r1, uint32_t& r2,
                                         uint32_t& r3, uint32_t addr) {
    asm volatile("ldmatrix.sync.aligned.m8n8.x4.trans.shared.b16 {%0,%1,%2,%3}, [%4];"
                 : "=r"(r0), "=r"(r1), "=r"(r2), "=r"(r3) : "r"(addr));
}
__device__ __forceinline__ void mma_bf16(float* c, const uint32_t* a, const uint32_t* b) {
    asm volatile(
        "mma.sync.aligned.m16n8k16.row.col.f32.bf16.bf16.f32 "
        "{%0,%1,%2,%3}, {%4,%5,%6,%7}, {%8,%9}, {%0,%1,%2,%3};"
        : "+f"(c[0]), "+f"(c[1]), "+f"(c[2]), "+f"(c[3])
        : "r"(a[0]), "r"(a[1]), "r"(a[2]), "r"(a[3]), "r"(b[0]), "r"(b[1]));
}
__device__ __forceinline__ void cp16(uint32_t dst, const void* src, bool pred) {
    int sz = pred ? 16 : 0;
    asm volatile("cp.async.cg.shared.global [%0], [%1], 16, %2;"
                 :: "r"(dst), "l"(src), "r"(sz) : "memory");
}
#define CP_COMMIT() asm volatile("cp.async.commit_group;" ::: "memory")

// ============================================================
// Streaming weight conversion: fp32 -> bf16 hi/lo, layout preserved.
// ============================================================
__global__ void convert_split_kernel(const float4* __restrict__ src,
                                     uint2* __restrict__ dh,
                                     uint2* __restrict__ dl, int n4) {
    int i = blockIdx.x * blockDim.x + threadIdx.x;
    if (i >= n4) return;
    float4 v = src[i];
    __nv_bfloat16 h0 = __float2bfloat16(v.x), h1 = __float2bfloat16(v.y);
    __nv_bfloat16 h2 = __float2bfloat16(v.z), h3 = __float2bfloat16(v.w);
    uint2 hh, ll;
    hh.x = ((uint32_t)__bfloat16_as_ushort(h1) << 16) | __bfloat16_as_ushort(h0);
    hh.y = ((uint32_t)__bfloat16_as_ushort(h3) << 16) | __bfloat16_as_ushort(h2);
    __nv_bfloat16 l0 = __float2bfloat16(v.x - __bfloat162float(h0));
    __nv_bfloat16 l1 = __float2bfloat16(v.y - __bfloat162float(h1));
    __nv_bfloat16 l2 = __float2bfloat16(v.z - __bfloat162float(h2));
    __nv_bfloat16 l3 = __float2bfloat16(v.w - __bfloat162float(h3));
    ll.x = ((uint32_t)__bfloat16_as_ushort(l1) << 16) | __bfloat16_as_ushort(l0);
    ll.y = ((uint32_t)__bfloat16_as_ushort(l3) << 16) | __bfloat16_as_ushort(l2);
    dh[i] = hh;
    dl[i] = ll;
}

// ============================================================
// HMMA GEMM, 64x64 C tile, K=1024, split-bf16 (3 MMA), 3-stage cp.async,
// register-double-buffered fragments (software pipelined ldmatrix vs HMMA).
// MODE: 0=QKV, 1=OPROJ(+resid), 2=GATEUP(gather+swiglu->act), 3=DOWN(->eo)
// ============================================================
template <int MODE, int NN>
__global__ __launch_bounds__(256, 2) void mma_gemm(
    const __nv_bfloat16* __restrict__ Ah, const __nv_bfloat16* __restrict__ Al,
    const __nv_bfloat16* __restrict__ Bh, const __nv_bfloat16* __restrict__ Bl,
    const float* __restrict__ bias, const float* __restrict__ resid,
    float* __restrict__ Cout) {
    extern __shared__ __align__(1024) char dsm[];
    __shared__ int s_tok[64];

    const int tid = threadIdx.x, wid = tid >> 5, lane = tid & 31;
    const int wm = wid & 1, wn = wid >> 1;
    const int row0 = blockIdx.y * 64, col0 = blockIdx.x * 64;
    int e = 0, lb = 0, cnt = Tc;
    if (MODE >= 2) {
        if ((int)blockIdx.y >= g_ntiles) return;
        e = g_tile_e[blockIdx.y];
        lb = row0 - g_poff[e];
        cnt = g_cnt[e];
    }
    const __nv_bfloat16* Bhg = Bh + (MODE >= 2 ? (size_t)e * 1024 * NN : 0);
    const __nv_bfloat16* Blg = Bl + (MODE >= 2 ? (size_t)e * 1024 * NN : 0);

    uint32_t base = (smem_to_u32(dsm) + 1023) & ~1023u;

    if (MODE == 2 && tid < 64) s_tok[tid] = g_tok[row0 + tid];
    if (MODE == 2) __syncthreads();

    auto issue_stage = [&](int kb, uint32_t buf) {
        const int kbase = kb * 64;
#pragma unroll
        for (int i = 0; i < 2; i++) {
            int c = tid + 256 * i;
            int row = c >> 3, k8 = c & 7;
            uint32_t raw = row * 128 + k8 * 16;
            uint32_t sw = raw ^ ((raw >> 3) & 0x70);
            size_t o;
            bool pred = true;
            if (MODE == 2) {
                int tok = s_tok[row];
                pred = tok >= 0;
                o = (size_t)(pred ? tok : 0) * 1024 + kbase + k8 * 8;
            } else if (MODE == 3) {
                pred = (lb + row) < cnt;
                o = (size_t)(row0 + row) * 1024 + kbase + k8 * 8;
            } else {
                o = (size_t)(row0 + row) * 1024 + kbase + k8 * 8;
            }
            cp16(buf + sw, Ah + o, pred);
            cp16(buf + ASZ + sw, Al + o, pred);
        }
#pragma unroll
        for (int i = 0; i < 2; i++) {
            int c = tid + 256 * i;
            int row = c >> 3, k8 = c & 7;
            uint32_t raw = row * 128 + k8 * 16;
            uint32_t sw = raw ^ ((raw >> 3) & 0x70);
            size_t o = (size_t)(kbase + row) * NN + col0 + k8 * 8;
            cp16(buf + 2 * ASZ + sw, Bhg + o, true);
            cp16(buf + 2 * ASZ + BSZ + sw, Blg + o, true);
        }
        CP_COMMIT();
    };

    float acc[2][2][4] = {};

    const uint32_t a_raw0 = (uint32_t)(wm * 32 + (lane & 15)) * 128 + (lane >> 4) * 16;
    const int bm = lane >> 3;
    const uint32_t b_raw0 = (uint32_t)((bm & 1) * 8 + (lane & 7)) * 128 +
                            (uint32_t)(wn * 16 + (bm >> 1) * 8) * 2;

    // ---- software-pipelined compute: prefetch ks+1 frags during ks MMAs ----
    auto compute = [&](uint32_t buf) {
        uint32_t AH = buf, AL = buf + ASZ, BH = buf + 2 * ASZ, BL = BH + BSZ;
        uint32_t ah[2][2][4], al[2][2][4], bh[2][2][2], bl[2][2][2];

        // prologue: load ks=0 into slot 0
#pragma unroll
        for (int mi = 0; mi < 2; mi++) {
            uint32_t raw = a_raw0 + mi * 2048;
            uint32_t sw = raw ^ ((raw >> 3) & 0x70);
            ldm_x4(ah[0][mi][0], ah[0][mi][1], ah[0][mi][2], ah[0][mi][3], AH + sw);
            ldm_x4(al[0][mi][0], al[0][mi][1], al[0][mi][2], al[0][mi][3], AL + sw);
        }
        {
            uint32_t raw = b_raw0;
            uint32_t sw = raw ^ ((raw >> 3) & 0x70);
            ldm_x4_t(bh[0][0][0], bh[0][0][1], bh[0][1][0], bh[0][1][1], BH + sw);
            ldm_x4_t(bl[0][0][0], bl[0][0][1], bl[0][1][0], bl[0][1][1], BL + sw);
        }
#pragma unroll
        for (int ks = 0; ks < 4; ks++) {
            const int cur = ks & 1, nxt = cur ^ 1;
            if (ks < 3) {   // prefetch next ks fragments (independent of MMAs below)
#pragma unroll
                for (int mi = 0; mi < 2; mi++) {
                    uint32_t raw = a_raw0 + mi * 2048 + (ks + 1) * 32;
                    uint32_t sw = raw ^ ((raw >> 3) & 0x70);
                    ldm_x4(ah[nxt][mi][0], ah[nxt][mi][1], ah[nxt][mi][2],
                           ah[nxt][mi][3], AH + sw);
                    ldm_x4(al[nxt][mi][0], al[nxt][mi][1], al[nxt][mi][2],
                           al[nxt][mi][3], AL + sw);
                }
                uint32_t raw = b_raw0 + (ks + 1) * 2048;
                uint32_t sw = raw ^ ((raw >> 3) & 0x70);
                ldm_x4_t(bh[nxt][0][0], bh[nxt][0][1], bh[nxt][1][0], bh[nxt][1][1],
                         BH + sw);
                ldm_x4_t(bl[nxt][0][0], bl[nxt][0][1], bl[nxt][1][0], bl[nxt][1][1],
                         BL + sw);
            }
#pragma unroll
            for (int mi = 0; mi < 2; mi++)
#pragma unroll
                for (int ni = 0; ni < 2; ni++) {
                    mma_bf16(acc[mi][ni], ah[cur][mi], bh[cur][ni]);
                    mma_bf16(acc[mi][ni], ah[cur][mi], bl[cur][ni]);
                    mma_bf16(acc[mi][ni], al[cur][mi], bh[cur][ni]);
                }
        }
    };

    issue_stage(0, base);
    issue_stage(1, base + STAGE);
    issue_stage(2, base + 2 * STAGE);
    for (int kb = 0; kb < 16; kb++) {
        if (kb < 14)
            asm volatile("cp.async.wait_group 2;" ::: "memory");
        else if (kb == 14)
            asm volatile("cp.async.wait_group 1;" ::: "memory");
        else
            asm volatile("cp.async.wait_group 0;" ::: "memory");
        __syncthreads();
        uint32_t buf = base + (uint32_t)(kb % 3) * STAGE;
        compute(buf);
        __syncthreads();
        if (kb + 3 < 16) issue_stage(kb + 3, buf);
    }

    // ---- epilogue ----
    const int g = lane >> 2, tg = lane & 3;
#pragma unroll
    for (int mi = 0; mi < 2; mi++) {
#pragma unroll
        for (int ni = 0; ni < 2; ni++) {
#pragma unroll
            for (int hh = 0; hh < 2; hh++) {
                int rt = wm * 32 + mi * 16 + g + hh * 8;
                int c = col0 + wn * 16 + ni * 8 + tg * 2;
                float v0 = acc[mi][ni][2 * hh + 0];
                float v1 = acc[mi][ni][2 * hh + 1];
                if (MODE == 0) {
                    size_t p = (size_t)(row0 + rt) * NN + c;
                    Cout[p] = v0 + bias[c];
                    Cout[p + 1] = v1 + bias[c + 1];
                } else if (MODE == 1) {
                    size_t p = (size_t)(row0 + rt) * NN + c;
                    Cout[p] = v0 + bias[c] + resid[p];
                    Cout[p + 1] = v1 + bias[c + 1] + resid[p + 1];
                } else if (MODE == 2) {
                    if (lb + rt < cnt) {
                        const float* bg = bias + (size_t)e * 2 * FFNc;
                        float gv = v0 + bg[c];
                        float uv = v1 + bg[c + 1];
                        gv = fminf(gv, LIMITc);
                        uv = fminf(fmaxf(uv, -LIMITc), LIMITc);
                        float glu = gv / (1.0f + expf(-ALPHAc * gv));
                        float a = (uv + 1.0f) * glu;
                        __nv_bfloat16 h = __float2bfloat16(a);
                        __nv_bfloat16 l = __float2bfloat16(a - __bfloat162float(h));
                        size_t p = (size_t)(row0 + rt) * FFNc + (c >> 1);
                        g_act_hi[p] = h;
                        g_act_lo[p] = l;
                    }
                } else {
                    if (lb + rt < cnt) {
                        const float* bd = bias + (size_t)e * Hc;
                        size_t p = (size_t)(row0 + rt) * Hc + c;
                        g_eo[p] = v0 + bd[c];
                        g_eo[p + 1] = v1 + bd[c + 1];
                    }
                }
            }
        }
    }
}

// ============================================================
// RMSNorm (ln1) -> bf16 hi/lo split
// ============================================================
__global__ void rmsnorm1_kernel(const float* __restrict__ x,
                                const float* __restrict__ w) {
    int t = blockIdx.x, tid = threadIdx.x;
    const float* xr = x + (size_t)t * Hc;
    float ss = 0.f;
#pragma unroll
    for (int i = 0; i < 4; i++) { float v = xr[tid + 256 * i]; ss += v * v; }
#pragma unroll
    for (int o = 16; o; o >>= 1) ss += __shfl_xor_sync(~0u, ss, o);
    __shared__ float red[8];
    if ((tid & 31) == 0) red[tid >> 5] = ss;
    __syncthreads();
    float tot = 0.f;
#pragma unroll
    for (int i = 0; i < 8; i++) tot += red[i];
    float rinv = rsqrtf(tot * (1.0f / Hc) + EPSc);
#pragma unroll
    for (int i = 0; i < 4; i++) {
        int c = tid + 256 * i;
        float v = xr[c] * w[c] * rinv;
        __nv_bfloat16 h = __float2bfloat16(v);
        g_xnh[(size_t)t * Hc + c] = h;
        g_xnl[(size_t)t * Hc + c] = __float2bfloat16(v - __bfloat162float(h));
    }
}

// ============================================================
// Tiled windowed GQA attention with sink
// ============================================================
__global__ __launch_bounds__(256, 1) void attn_kernel(
    const float* __restrict__ qkvb, const float* __restrict__ kvc,
    const int* __restrict__ pidx, const float* __restrict__ sinks) {
    extern __shared__ float sm[];
    float* Ks = sm;
    float* Vs = Ks + AT_KV;
    float* Qs = Vs + AT_KV;
    float* Ss = Qs + AT_Q;
    float* Rd = Ss + AT_S;

    const int qt = blockIdx.x, kvh = blockIdx.y, b = blockIdx.z;
    const int q0 = qt * 16;
    const int tid = threadIdx.x;

    for (int i = tid; i < 143 * 16; i += 256) {
        int kk = i >> 4, d = (i & 15) * 4;
        int kpos = 769 + q0 + kk;
        const float *kp, *vp;
        if (kpos >= Sq - Qc) {
            int tt = b * Qc + (kpos - (Sq - Qc));
            kp = qkvb + (size_t)tt * QKVW + (NQc + kvh) * HDc + d;
            vp = qkvb + (size_t)tt * QKVW + (NQc + NKVc + kvh) * HDc + d;
        } else {
            int pg = pidx[b * Pc + (kpos >> 7)];
            size_t bb = ((size_t)(pg * 2) * PSc + (kpos & 127)) * (NKVc * HDc) + kvh * HDc + d;
            kp = kvc + bb;
            vp = kvc + bb + (size_t)PSc * NKVc * HDc;
        }
        *(float4*)(Ks + kk * 68 + d) = *(const float4*)kp;
        *(float4*)(Vs + kk * 68 + d) = *(const float4*)vp;
    }
    for (int i = tid; i < 1024; i += 256) {
        int h = i >> 8, qq = (i >> 4) & 15, d = (i & 15) * 4;
        int t = b * Qc + q0 + qq;
        float4 v = *(const float4*)(qkvb + (size_t)t * QKVW + (kvh * 4 + h) * HDc + d);
        v.x *= SCALEc; v.y *= SCALEc; v.z *= SCALEc; v.w *= SCALEc;
        *(float4*)(Qs + (h * 16 + qq) * 64 + d) = v;
    }
    __syncthreads();

    {
        const int qq = tid >> 4, lane = tid & 15;
        float acc[8][4];
#pragma unroll
        for (int j = 0; j < 8; j++)
#pragma unroll
            for (int h = 0; h < 4; h++) acc[j][h] = 0.f;
#pragma unroll
        for (int dc = 0; dc < 4; dc++) {
            float4 qr[4][4];
#pragma unroll
            for (int h = 0; h < 4; h++)
#pragma unroll
                for (int dd = 0; dd < 4; dd++)
                    qr[h][dd] = *(float4*)(Qs + (h * 16 + qq) * 64 + dc * 16 + dd * 4);
#pragma unroll
            for (int j = 0; j < 8; j++) {
                int kk = qq + lane + 16 * j;
                const float* kr = Ks + kk * 68 + dc * 16;
#pragma unroll
                for (int dd = 0; dd < 4; dd++) {
                    float4 k4 = *(const float4*)(kr + dd * 4);
#pragma unroll
                    for (int h = 0; h < 4; h++)
                        acc[j][h] += qr[h][dd].x * k4.x + qr[h][dd].y * k4.y +
                                     qr[h][dd].z * k4.z + qr[h][dd].w * k4.w;
                }
            }
        }
#pragma unroll
        for (int j = 0; j < 8; j++) {
            int l = lane + 16 * j;
#pragma unroll
            for (int h = 0; h < 4; h++) Ss[(qq * 128 + l) * 4 + h] = acc[j][h];
        }
    }
    __syncthreads();

    {
        const int row = tid >> 2, l2 = tid & 3;
        const int sq = row >> 2, sh = row & 3;
        float m = -1e30f;
        for (int k = l2; k < 128; k += 4) m = fmaxf(m, Ss[(sq * 128 + k) * 4 + sh]);
        m = fmaxf(m, __shfl_xor_sync(~0u, m, 1));
        m = fmaxf(m, __shfl_xor_sync(~0u, m, 2));
        float sum = 0.f;
        for (int k = l2; k < 128; k += 4) {
            float p = expf(Ss[(sq * 128 + k) * 4 + sh] - m);
            Ss[(sq * 128 + k) * 4 + sh] = p;
            sum += p;
        }
        sum += __shfl_xor_sync(~0u, sum, 1);
        sum += __shfl_xor_sync(~0u, sum, 2);
        if (l2 == 0) Rd[sq * 4 + sh] = 1.0f / (sum + expf(sinks[kvh * 4 + sh] - m));
    }
    __syncthreads();

    {
        const int qq = tid >> 4, lane = tid & 15;
        const int d = lane * 4;
        float4 oa[4];
#pragma unroll
        for (int h = 0; h < 4; h++) oa[h] = make_float4(0.f, 0.f, 0.f, 0.f);
        for (int l = 0; l < 128; l++) {
            float4 v = *(const float4*)(Vs + (qq + l) * 68 + d);
            const float* pr = Ss + (qq * 128 + l) * 4;
#pragma unroll
            for (int h = 0; h < 4; h++) {
                float p = pr[h];
                oa[h].x += p * v.x; oa[h].y += p * v.y;
                oa[h].z += p * v.z; oa[h].w += p * v.w;
            }
        }
        int t = b * Qc + q0 + qq;
#pragma unroll
        for (int h = 0; h < 4; h++) {
            float r = Rd[qq * 4 + h];
            float x0 = oa[h].x * r, x1 = oa[h].y * r, x2 = oa[h].z * r, x3 = oa[h].w * r;
            size_t p2 = (size_t)t * Hc + (kvh * 4 + h) * HDc + d;
            uint2 hh, ll;
            __nv_bfloat16 b0 = __float2bfloat16(x0), b1 = __float2bfloat16(x1);
            __nv_bfloat16 b2 = __float2bfloat16(x2), b3 = __float2bfloat16(x3);
            hh.x = ((uint32_t)__bfloat16_as_ushort(b1) << 16) | __bfloat16_as_ushort(b0);
            hh.y = ((uint32_t)__bfloat16_as_ushort(b3) << 16) | __bfloat16_as_ushort(b2);
            __nv_bfloat16 c0 = __float2bfloat16(x0 - __bfloat162float(b0));
            __nv_bfloat16 c1 = __float2bfloat16(x1 - __bfloat162float(b1));
            __nv_bfloat16 c2 = __float2bfloat16(x2 - __bfloat162float(b2));
            __nv_bfloat16 c3 = __float2bfloat16(x3 - __bfloat162float(b3));
            ll.x = ((uint32_t)__bfloat16_as_ushort(c1) << 16) | __bfloat16_as_ushort(c0);
            ll.y = ((uint32_t)__bfloat16_as_ushort(c3) << 16) | __bfloat16_as_ushort(c2);
            *(uint2*)(g_ath + p2) = hh;
            *(uint2*)(g_atl + p2) = ll;
        }
    }
}

// ============================================================
// Router: rmsnorm(ln2) -> x2 (bf16 split), logits, top-2 weights
// ============================================================
__global__ void router_kernel(const float* __restrict__ ln2,
                              const float* __restrict__ Wr,
                              const float* __restrict__ br) {
    int t = blockIdx.x, tid = threadIdx.x;
    __shared__ float sx[Hc];
    __shared__ float red[8];
    __shared__ float lg[Ec];
    const float* hr = g_h + (size_t)t * Hc;
    float ss = 0.f;
#pragma unroll
    for (int i = 0; i < 4; i++) { float v = hr[tid + 256 * i]; ss += v * v; }
#pragma unroll
    for (int o = 16; o; o >>= 1) ss += __shfl_xor_sync(~0u, ss, o);
    if ((tid & 31) == 0) red[tid >> 5] = ss;
    __syncthreads();
    float tot = 0.f;
#pragma unroll
    for (int i = 0; i < 8; i++) tot += red[i];
    float rinv = rsqrtf(tot * (1.0f / Hc) + EPSc);
#pragma unroll
    for (int i = 0; i < 4; i++) {
        int c = tid + 256 * i;
        float v = hr[c] * ln2[c] * rinv;
        sx[c] = v;
        __nv_bfloat16 hb = __float2bfloat16(v);
        g_x2h[(size_t)t * Hc + c] = hb;
        g_x2l[(size_t)t * Hc + c] = __float2bfloat16(v - __bfloat162float(hb));
    }
    __syncthreads();
    int w = tid >> 5, lane = tid & 31;
    float s = 0.f;
    for (int c = lane; c < Hc; c += 32) s += sx[c] * Wr[c * Ec + w];
#pragma unroll
    for (int o = 16; o; o >>= 1) s += __shfl_xor_sync(~0u, s, o);
    if (lane == 0) lg[w] = s + br[w];
    __syncthreads();
    if (tid == 0) {
        int i0 = 0; float v0 = lg[0];
#pragma unroll
        for (int e = 1; e < Ec; e++) if (lg[e] > v0) { v0 = lg[e]; i0 = e; }
        int i1 = -1; float v1 = -1e30f;
#pragma unroll
        for (int e = 0; e < Ec; e++) {
            if (e == i0) continue;
            if (lg[e] > v1) { v1 = lg[e]; i1 = e; }
        }
        float e1 = expf(v1 - v0);
        g_eidx[t * 2] = i0; g_eidx[t * 2 + 1] = i1;
        g_ewt[t * 2] = 1.0f / (1.0f + e1);
        g_ewt[t * 2 + 1] = e1 / (1.0f + e1);
    }
}

// ============================================================
// Bucket tokens by expert with 64-aligned padded regions + tile map
// ============================================================
__global__ void bucket_kernel() {
    __shared__ int c1[Ec], c2[Ec], po[Ec];
    int tid = threadIdx.x;
    if (tid < Ec) { c1[tid] = 0; c2[tid] = 0; }
    for (int i = tid; i < SLOTS; i += 256) g_tok[i] = -1;
    __syncthreads();
    for (int i = tid; i < Tc * 2; i += 256) atomicAdd(&c1[g_eidx[i]], 1);
    __syncthreads();
    if (tid == 0) {
        int run = 0, nt = 0;
        for (int e = 0; e < Ec; e++) {
            po[e] = run;
            g_poff[e] = run;
            int te = (c1[e] + 63) >> 6;
            for (int j = 0; j < te; j++) g_tile_e[nt++] = e;
            run += te * 64;
        }
        g_ntiles = nt;
    }
    __syncthreads();
    if (tid < Ec) g_cnt[tid] = c1[tid];
    for (int i = tid; i < Tc * 2; i += 256) {
        int e = g_eidx[i];
        int r = atomicAdd(&c2[e], 1);
        int slot = po[e] + r;
        g_tok[slot] = i >> 1;
        g_slotof[i] = slot;
    }
}

// ============================================================
// Final combine
// ============================================================
__global__ void combine_kernel(float* __restrict__ out) {
    int t = blockIdx.x, tid = threadIdx.x;
    float w0 = g_ewt[t * 2], w1 = g_ewt[t * 2 + 1];
    int s0 = g_slotof[t * 2], s1 = g_slotof[t * 2 + 1];
#pragma unroll
    for (int i = 0; i < 4; i++) {
        int c = tid + 256 * i;
        out[(size_t)t * Hc + c] = g_h[(size_t)t * Hc + c]
                                + w0 * g_eo[(size_t)s0 * Hc + c]
                                + w1 * g_eo[(size_t)s1 * Hc + c];
    }
}

// ============================================================
extern "C" void kernel_launch(void* const* d_in, const int* in_sizes, int n_in,
                              void* d_out, int out_size) {
    const float* hidden = (const float*)d_in[0];
    const float* kvc    = (const float*)d_in[1];
    const int*   pidx   = (const int*)d_in[3];
    const float* sinks  = (const float*)d_in[4];
    const float* w_qkv  = (const float*)d_in[5];
    const float* b_qkv  = (const float*)d_in[6];
    const float* w_o    = (const float*)d_in[7];
    const float* b_o    = (const float*)d_in[8];
    const float* ln1    = (const float*)d_in[9];
    const float* ln2    = (const float*)d_in[10];
    const float* w_r    = (const float*)d_in[11];
    const float* b_r    = (const float*)d_in[12];
    const float* w_gu   = (const float*)d_in[13];
    const float* b_gu   = (const float*)d_in[14];
    const float* w_d    = (const float*)d_in[15];
    const float* b_d    = (const float*)d_in[16];
    float* out = (float*)d_out;

    void *pq, *ph;
    void *pxh, *pxl, *pah, *pal, *px2h, *px2l, *pacth, *pactl;
    void *pwqh, *pwql, *pwoh, *pwol, *pwguh, *pwgul, *pwdh, *pwdl;
    cudaGetSymbolAddress(&pq, g_qkv);
    cudaGetSymbolAddress(&ph, g_h);
    cudaGetSymbolAddress(&pxh, g_xnh);  cudaGetSymbolAddress(&pxl, g_xnl);
    cudaGetSymbolAddress(&pah, g_ath);  cudaGetSymbolAddress(&pal, g_atl);
    cudaGetSymbolAddress(&px2h, g_x2h); cudaGetSymbolAddress(&px2l, g_x2l);
    cudaGetSymbolAddress(&pacth, g_act_hi); cudaGetSymbolAddress(&pactl, g_act_lo);
    cudaGetSymbolAddress(&pwqh, g_wqh); cudaGetSymbolAddress(&pwql, g_wql);
    cudaGetSymbolAddress(&pwoh, g_woh); cudaGetSymbolAddress(&pwol, g_wol);
    cudaGetSymbolAddress(&pwguh, g_wguh); cudaGetSymbolAddress(&pwgul, g_wgul);
    cudaGetSymbolAddress(&pwdh, g_wdh);   cudaGetSymbolAddress(&pwdl, g_wdl);

    cudaFuncSetAttribute(mma_gemm<0, QKVW>, cudaFuncAttributeMaxDynamicSharedMemorySize, GEMM_SMEM);
    cudaFuncSetAttribute(mma_gemm<1, Hc>, cudaFuncAttributeMaxDynamicSharedMemorySize, GEMM_SMEM);
    cudaFuncSetAttribute(mma_gemm<2, 2 * FFNc>, cudaFuncAttributeMaxDynamicSharedMemorySize, GEMM_SMEM);
    cudaFuncSetAttribute(mma_gemm<3, Hc>, cudaFuncAttributeMaxDynamicSharedMemorySize, GEMM_SMEM);
    cudaFuncSetAttribute(attn_kernel, cudaFuncAttributeMaxDynamicSharedMemorySize, ATT_SMEM);

    // ---- side stream for weight converts (fork/join, capture-safe) ----
    cudaStream_t s1;
    cudaStreamCreate(&s1);
    cudaEvent_t e0, e1, e2;
    cudaEventCreateWithFlags(&e0, cudaEventDisableTiming);
    cudaEventCreateWithFlags(&e1, cudaEventDisableTiming);
    cudaEventCreateWithFlags(&e2, cudaEventDisableTiming);

    cudaEventRecord(e0, 0);
    cudaStreamWaitEvent(s1, e0, 0);
    {
        int n4;
        n4 = Hc * QKVW / 4;
        convert_split_kernel<<<(n4 + 255) / 256, 256, 0, s1>>>(
            (const float4*)w_qkv, (uint2*)pwqh, (uint2*)pwql, n4);
        n4 = Hc * Hc / 4;
        convert_split_kernel<<<(n4 + 255) / 256, 256, 0, s1>>>(
            (const float4*)w_o, (uint2*)pwoh, (uint2*)pwol, n4);
        cudaEventRecord(e1, s1);
        n4 = Ec * Hc * 2 * FFNc / 4;
        convert_split_kernel<<<(n4 + 255) / 256, 256, 0, s1>>>(
            (const float4*)w_gu, (uint2*)pwguh, (uint2*)pwgul, n4);
        n4 = Ec * FFNc * Hc / 4;
        convert_split_kernel<<<(n4 + 255) / 256, 256, 0, s1>>>(
            (const float4*)w_d, (uint2*)pwdh, (uint2*)pwdl, n4);
        cudaEventRecord(e2, s1);
    }

    // main stream
    rmsnorm1_kernel<<<Tc, 256>>>(hidden, ln1);
    cudaStreamWaitEvent(0, e1, 0);
    mma_gemm<0, QKVW><<<dim3(QKVW / 64, Tc / 64, 1), 256, GEMM_SMEM>>>(
        (const __nv_bfloat16*)pxh, (const __nv_bfloat16*)pxl,
        (const __nv_bfloat16*)pwqh, (const __nv_bfloat16*)pwql,
        b_qkv, nullptr, (float*)pq);
    attn_kernel<<<dim3(8, NKVc, Bc), 256, ATT_SMEM>>>(
        (const float*)pq, kvc, pidx, sinks);
    mma_gemm<1, Hc><<<dim3(Hc / 64, Tc / 64, 1), 256, GEMM_SMEM>>>(
        (const __nv_bfloat16*)pah, (const __nv_bfloat16*)pal,
        (const __nv_bfloat16*)pwoh, (const __nv_bfloat16*)pwol,
        b_o, hidden, (float*)ph);
    router_kernel<<<Tc, 256>>>(ln2, w_r, b_r);
    bucket_kernel<<<1, 256>>>();
    cudaStreamWaitEvent(0, e2, 0);
    mma_gemm<2, 2 * FFNc><<<dim3(2 * FFNc / 64, MAXTILES, 1), 256, GEMM_SMEM>>>(
        (const __nv_bfloat16*)px2h, (const __nv_bfloat16*)px2l,
        (const __nv_bfloat16*)pwguh, (const __nv_bfloat16*)pwgul,
        b_gu, nullptr, nullptr);
    mma_gemm<3, Hc><<<dim3(Hc / 64, MAXTILES, 1), 256, GEMM_SMEM>>>(
        (const __nv_bfloat16*)pacth, (const __nv_bfloat16*)pactl,
        (const __nv_bfloat16*)pwdh, (const __nv_bfloat16*)pwdl,
        b_d, nullptr, nullptr);
    combine_kernel<<<Tc, 256>>>(out);
}